// round 8
// baseline (speedup 1.0000x reference)
#include <cuda_runtime.h>
#include <cuda_fp16.h>
#include <stdint.h>
#include <math.h>

#define H       1024
#define O_DIM   8192
#define T_STEPS 64
#define B_SZ    256
#define BH      (B_SZ * H)
#define K2      (2 * H)

#define PAD_R   72     // rnn smem pitch (halves), BK=64
#define PAD_F   40     // fc smem pitch (halves),  BK=32
// rnn stage (halves): Ah 0 (64x72=4608), Al 4608, Bh 9216 (64x72), Bl 13824 ; stage=18432
#define R_AL    4608
#define R_BH    9216
#define R_BL    13824
#define R_STG   18432
// fc stage (halves): Ah 0 (128x40), Al 5120, B 10240 (256x40) ; stage=20480
#define F_AL    5120
#define F_B     10240
#define F_STG   20480

// ---- device scratch (static) ----
__device__ __half g_Wcat_hi[2 * H * K2];
__device__ __half g_Wcat_lo[2 * H * K2];
__device__ __half g_fcW_hi[O_DIM * H];
__device__ __half g_outs_hi[(T_STEPS + 1) * BH];
__device__ __half g_outs_lo[(T_STEPS + 1) * BH];
__device__ __half g_h0_hi[2 * BH];
__device__ __half g_h0_lo[2 * BH];
__device__ __half g_h1i_hi[BH];
__device__ __half g_h1i_lo[BH];

__device__ __forceinline__ void split2(float v, __half &hi, __half &lo) {
    hi = __float2half(v);
    lo = __float2half(v - __half2float(hi));
}

// ---- prep kernels ----
__global__ void prep_wcat_kernel(const float* __restrict__ W_ih,
                                 const float* __restrict__ W_hh) {
    int idx = blockIdx.x * blockDim.x + threadIdx.x;
    if (idx >= 2 * H * K2) return;
    int l = idx / (H * K2);
    int rem = idx - l * (H * K2);
    int n = rem / K2, k = rem - n * K2;
    float w = (k < H) ? W_ih[(l * H + n) * H + k] : W_hh[(l * H + n) * H + (k - H)];
    split2(w, g_Wcat_hi[idx], g_Wcat_lo[idx]);
}
__global__ void prep_fcw_kernel(const float* __restrict__ fcW) {
    int idx = blockIdx.x * blockDim.x + threadIdx.x;
    if (idx >= O_DIM * H) return;
    g_fcW_hi[idx] = __float2half(fcW[idx]);
}
__global__ void prep_acts_kernel(const float* __restrict__ x,
                                 const float* __restrict__ hidden) {
    int idx = blockIdx.x * blockDim.x + threadIdx.x;
    if (idx >= 3 * BH) return;
    if (idx < BH)            split2(x[idx], g_outs_hi[idx], g_outs_lo[idx]);
    else if (idx < 2 * BH) { int j = idx - BH;     split2(hidden[j],      g_h0_hi[j],  g_h0_lo[j]); }
    else                   { int j = idx - 2 * BH; split2(hidden[BH + j], g_h1i_hi[j], g_h1i_lo[j]); }
}

// ---- helpers ----
__device__ __forceinline__ void cpasync16(void* dst, const void* src) {
    uint32_t d = (uint32_t)__cvta_generic_to_shared(dst);
    asm volatile("cp.async.cg.shared.global [%0], [%1], 16;" :: "r"(d), "l"(src));
}
__device__ __forceinline__ void cp_commit() { asm volatile("cp.async.commit_group;"); }
template <int N> __device__ __forceinline__ void cp_wait() {
    asm volatile("cp.async.wait_group %0;" :: "n"(N));
}
__device__ __forceinline__ uint32_t lds32(const __half* p) {
    return *reinterpret_cast<const uint32_t*>(p);
}
__device__ __forceinline__ void mma_f16(float* c, const uint32_t* a, const uint32_t* b) {
    asm volatile(
        "mma.sync.aligned.m16n8k16.row.col.f32.f16.f16.f32 "
        "{%0,%1,%2,%3}, {%4,%5,%6,%7}, {%8,%9}, {%0,%1,%2,%3};"
        : "+f"(c[0]), "+f"(c[1]), "+f"(c[2]), "+f"(c[3])
        : "r"(a[0]), "r"(a[1]), "r"(a[2]), "r"(a[3]), "r"(b[0]), "r"(b[1]));
}

// ---- RNN step: C = tanh([A1|A2] @ Wcat^T + b1 + b2); M=256,N=1024,K=2048
// grid (16,4)=64 blocks, tile 64m x 64n, 512 thr (16 warps 4m x 4n, warp 16x16)
// per-warp compute/epilogue IDENTICAL to proven round-4/7 path (wm=wid>>2, wn=wid&3)
// 4-stage cp.async, lds32 fragments, 3 independent accumulator chains
__global__ __launch_bounds__(512) void rnn_step_kernel(
    const __half* __restrict__ A1h, const __half* __restrict__ A1l,
    const __half* __restrict__ A2h, const __half* __restrict__ A2l,
    const __half* __restrict__ Bh,  const __half* __restrict__ Bl,
    const float* __restrict__ bias1, const float* __restrict__ bias2,
    __half* __restrict__ Ch, __half* __restrict__ Cl)
{
    extern __shared__ __align__(16) __half smem[];
    const int tid = threadIdx.x;
    const int by64 = blockIdx.y * 64, bx64 = blockIdx.x * 64;

    auto prefetch = [&](int kc, int st) {
        __half* base = smem + st * R_STG;
        const bool low = (kc < 16);
        const int k0 = (low ? kc : kc - 16) * 64;
        const __half* Ah = low ? A1h : A2h;
        const __half* Al = low ? A1l : A2l;
        #pragma unroll
        for (int i = 0; i < 2; i++) {           // A hi+lo: 64 rows x 64k -> 1024 chunks
            int chunk = i * 512 + tid;
            int mat = chunk >> 9, rem = chunk & 511;
            int r = rem >> 3, c = (rem & 7) * 8;
            cpasync16(base + mat * R_AL + r * PAD_R + c,
                      (mat ? Al : Ah) + (size_t)(by64 + r) * H + k0 + c);
        }
        const int kb = kc * 64;
        #pragma unroll
        for (int i = 0; i < 2; i++) {           // B hi+lo: 64 rows x 64k -> 1024 chunks
            int chunk = i * 512 + tid;
            int mat = chunk >> 9, rem = chunk & 511;
            int r = rem >> 3, c = (rem & 7) * 8;
            cpasync16(base + R_BH + mat * R_AL + r * PAD_R + c,
                      (mat ? Bl : Bh) + (size_t)(bx64 + r) * K2 + kb + c);
        }
    };

    float accA[2][4], accB[2][4], accC[2][4];
    #pragma unroll
    for (int nt = 0; nt < 2; nt++)
        #pragma unroll
        for (int i = 0; i < 4; i++) { accA[nt][i] = 0.f; accB[nt][i] = 0.f; accC[nt][i] = 0.f; }

    const int lane = tid & 31, wid = tid >> 5;
    const int g = lane >> 2, tg = lane & 3;
    const int wm = wid >> 2, wn = wid & 3;   // 4 m-warps x 4 n-warps

    prefetch(0, 0); cp_commit();
    prefetch(1, 1); cp_commit();
    prefetch(2, 2); cp_commit();

    for (int kc = 0; kc < 32; kc++) {
        const int st = kc & 3;
        __syncthreads();
        if (kc + 3 < 32) { prefetch(kc + 3, (kc + 3) & 3); cp_commit(); cp_wait<3>(); }
        else if (kc == 29) cp_wait<2>();
        else if (kc == 30) cp_wait<1>();
        else               cp_wait<0>();

        const __half* pAh = smem + st * R_STG;
        const __half* pAl = pAh + R_AL;
        const __half* pBh = pAh + (R_BH - 0);
        const __half* pBl = pAh + R_BL;
        #pragma unroll
        for (int kk = 0; kk < 4; kk++) {
            const int c0 = kk * 16 + tg * 2;
            const int rm = wm * 16 + g;
            uint32_t afh[4], afl[4];
            afh[0] = lds32(pAh + rm * PAD_R + c0);
            afh[1] = lds32(pAh + (rm + 8) * PAD_R + c0);
            afh[2] = lds32(pAh + rm * PAD_R + c0 + 8);
            afh[3] = lds32(pAh + (rm + 8) * PAD_R + c0 + 8);
            afl[0] = lds32(pAl + rm * PAD_R + c0);
            afl[1] = lds32(pAl + (rm + 8) * PAD_R + c0);
            afl[2] = lds32(pAl + rm * PAD_R + c0 + 8);
            afl[3] = lds32(pAl + (rm + 8) * PAD_R + c0 + 8);
            #pragma unroll
            for (int nt = 0; nt < 2; nt++) {
                int n = wn * 16 + nt * 8 + g;
                uint32_t bh[2] = { lds32(pBh + n * PAD_R + c0), lds32(pBh + n * PAD_R + c0 + 8) };
                uint32_t bl[2] = { lds32(pBl + n * PAD_R + c0), lds32(pBl + n * PAD_R + c0 + 8) };
                mma_f16(accA[nt], afh, bh);
                mma_f16(accB[nt], afl, bh);
                mma_f16(accC[nt], afh, bl);
            }
        }
    }

    #pragma unroll
    for (int nt = 0; nt < 2; nt++) {
        int r = by64 + wm * 16 + g;
        int c = bx64 + wn * 16 + nt * 8 + tg * 2;
        float bb0 = bias1[c] + bias2[c];
        float bb1 = bias1[c + 1] + bias2[c + 1];
        float v0 = tanhf(accA[nt][0] + accB[nt][0] + accC[nt][0] + bb0);
        float v1 = tanhf(accA[nt][1] + accB[nt][1] + accC[nt][1] + bb1);
        float v2 = tanhf(accA[nt][2] + accB[nt][2] + accC[nt][2] + bb0);
        float v3 = tanhf(accA[nt][3] + accB[nt][3] + accC[nt][3] + bb1);
        __half h0, l0, h1, l1; __half2 t;
        split2(v0, h0, l0); split2(v1, h1, l1);
        t.x = h0; t.y = h1; *reinterpret_cast<__half2*>(&Ch[r * H + c]) = t;
        t.x = l0; t.y = l1; *reinterpret_cast<__half2*>(&Cl[r * H + c]) = t;
        split2(v2, h0, l0); split2(v3, h1, l1);
        t.x = h0; t.y = h1; *reinterpret_cast<__half2*>(&Ch[(r + 8) * H + c]) = t;
        t.x = l0; t.y = l1; *reinterpret_cast<__half2*>(&Cl[(r + 8) * H + c]) = t;
    }
}

// ---- FC (full) [ROUND-7 VERBATIM]: out = A @ fcW^T + fc_b ; M=16384,N=8192,K=1024
// grid (32,128)=4096, tile 128m x 256n, 512 thr (16 warps 4m x 4n, warp 32x64)
// fp16 2-pass, 2-stage cp.async, lds32 fragments
__global__ __launch_bounds__(512) void fc_kernel(
    const __half* __restrict__ Ah, const __half* __restrict__ Al,
    const __half* __restrict__ Bh,
    const float* __restrict__ fcb, float* __restrict__ outp)
{
    extern __shared__ __align__(16) __half smem[];
    const int tid = threadIdx.x;
    const int row0 = blockIdx.y * 128, col0 = blockIdx.x * 256;

    auto prefetch = [&](int kc, int st) {
        __half* base = smem + st * F_STG;
        const int k0 = kc * 32;
        #pragma unroll
        for (int i = 0; i < 2; i++) {           // A hi+lo: 1024 chunks
            int chunk = i * 512 + tid;
            int mat = chunk >> 9, rem = chunk & 511;
            int r = rem >> 2, c = (rem & 3) * 8;
            cpasync16(base + mat * F_AL + r * PAD_F + c,
                      (mat ? Al : Ah) + (size_t)(row0 + r) * H + k0 + c);
        }
        #pragma unroll
        for (int i = 0; i < 2; i++) {           // B: 1024 chunks (256 rows)
            int chunk = i * 512 + tid;
            int r = chunk >> 2, c = (chunk & 3) * 8;
            cpasync16(base + F_B + r * PAD_F + c,
                      Bh + (size_t)(col0 + r) * H + k0 + c);
        }
    };

    float acc[2][8][4];
    #pragma unroll
    for (int mt = 0; mt < 2; mt++)
        #pragma unroll
        for (int nt = 0; nt < 8; nt++)
            #pragma unroll
            for (int i = 0; i < 4; i++) acc[mt][nt][i] = 0.f;

    const int lane = tid & 31, wid = tid >> 5;
    const int g = lane >> 2, tg = lane & 3;
    const int wm = wid >> 2, wn = wid & 3;   // 4 m-warps x 4 n-warps

    prefetch(0, 0); cp_commit();
    for (int kc = 0; kc < 32; kc++) {
        int st = kc & 1;
        if (kc + 1 < 32) { prefetch(kc + 1, st ^ 1); cp_commit(); cp_wait<1>(); }
        else             { cp_wait<0>(); }
        __syncthreads();
        const __half* pAh = smem + st * F_STG;
        const __half* pAl = pAh + F_AL;
        const __half* pB  = pAh + F_B;
        #pragma unroll
        for (int kk = 0; kk < 2; kk++) {
            const int c0 = kk * 16 + tg * 2;
            uint32_t afh[2][4], afl[2][4];
            #pragma unroll
            for (int mt = 0; mt < 2; mt++) {
                int rm = wm * 32 + mt * 16 + g;
                afh[mt][0] = lds32(pAh + rm * PAD_F + c0);
                afh[mt][1] = lds32(pAh + (rm + 8) * PAD_F + c0);
                afh[mt][2] = lds32(pAh + rm * PAD_F + c0 + 8);
                afh[mt][3] = lds32(pAh + (rm + 8) * PAD_F + c0 + 8);
                afl[mt][0] = lds32(pAl + rm * PAD_F + c0);
                afl[mt][1] = lds32(pAl + (rm + 8) * PAD_F + c0);
                afl[mt][2] = lds32(pAl + rm * PAD_F + c0 + 8);
                afl[mt][3] = lds32(pAl + (rm + 8) * PAD_F + c0 + 8);
            }
            #pragma unroll
            for (int nt = 0; nt < 8; nt++) {
                int n = wn * 64 + nt * 8 + g;
                uint32_t bh[2] = { lds32(pB + n * PAD_F + c0), lds32(pB + n * PAD_F + c0 + 8) };
                #pragma unroll
                for (int mt = 0; mt < 2; mt++) {
                    mma_f16(acc[mt][nt], afh[mt], bh);
                    mma_f16(acc[mt][nt], afl[mt], bh);
                }
            }
        }
        __syncthreads();
    }

    #pragma unroll
    for (int mt = 0; mt < 2; mt++) {
        #pragma unroll
        for (int nt = 0; nt < 8; nt++) {
            size_t r = row0 + wm * 32 + mt * 16 + g;
            int c = col0 + wn * 64 + nt * 8 + tg * 2;
            float b0 = fcb[c], b1 = fcb[c + 1];
            float2 p0 = { acc[mt][nt][0] + b0, acc[mt][nt][1] + b1 };
            float2 p1 = { acc[mt][nt][2] + b0, acc[mt][nt][3] + b1 };
            *reinterpret_cast<float2*>(&outp[r * O_DIM + c]) = p0;
            *reinterpret_cast<float2*>(&outp[(r + 8) * O_DIM + c]) = p1;
        }
    }
}

// ---- host launcher ----
extern "C" void kernel_launch(void* const* d_in, const int* in_sizes, int n_in,
                              void* d_out, int out_size) {
    const float* x      = (const float*)d_in[0];
    const float* hidden = (const float*)d_in[1];
    const float* W_ih   = (const float*)d_in[3];
    const float* W_hh   = (const float*)d_in[4];
    const float* b_ih   = (const float*)d_in[5];
    const float* b_hh   = (const float*)d_in[6];
    const float* fc_W   = (const float*)d_in[7];
    const float* fc_b   = (const float*)d_in[8];
    float* outp = (float*)d_out;

    __half *Wh, *Wl, *Fh, *Oh, *Ol, *H0h, *H0l, *H1h, *H1l;
    cudaGetSymbolAddress((void**)&Wh,  g_Wcat_hi);
    cudaGetSymbolAddress((void**)&Wl,  g_Wcat_lo);
    cudaGetSymbolAddress((void**)&Fh,  g_fcW_hi);
    cudaGetSymbolAddress((void**)&Oh,  g_outs_hi);
    cudaGetSymbolAddress((void**)&Ol,  g_outs_lo);
    cudaGetSymbolAddress((void**)&H0h, g_h0_hi);
    cudaGetSymbolAddress((void**)&H0l, g_h0_lo);
    cudaGetSymbolAddress((void**)&H1h, g_h1i_hi);
    cudaGetSymbolAddress((void**)&H1l, g_h1i_lo);

    const int rnn_smem = 4 * R_STG * (int)sizeof(__half);  // 147456
    const int fc_smem  = 2 * F_STG * (int)sizeof(__half);  // 81920
    cudaFuncSetAttribute(rnn_step_kernel, cudaFuncAttributeMaxDynamicSharedMemorySize, rnn_smem);
    cudaFuncSetAttribute(fc_kernel,       cudaFuncAttributeMaxDynamicSharedMemorySize, fc_smem);

    prep_wcat_kernel<<<(2 * H * K2 + 255) / 256, 256>>>(W_ih, W_hh);
    prep_fcw_kernel<<<(O_DIM * H + 255) / 256, 256>>>(fc_W);
    prep_acts_kernel<<<(3 * BH + 255) / 256, 256>>>(x, hidden);

    dim3 rgrid(H / 64, B_SZ / 64);   // (16, 4) = 64 blocks, 512 thr
    int p = 0;
    for (int t = 0; t < T_STEPS; t++) {
        rnn_step_kernel<<<rgrid, 512, rnn_smem>>>(
            Oh + (size_t)t * BH, Ol + (size_t)t * BH,
            H0h + (size_t)p * BH, H0l + (size_t)p * BH,
            Wh, Wl, b_ih, b_hh,
            H0h + (size_t)(p ^ 1) * BH, H0l + (size_t)(p ^ 1) * BH);
        const __half* h1h = (t == 0) ? H1h : Oh + (size_t)t * BH;
        const __half* h1l = (t == 0) ? H1l : Ol + (size_t)t * BH;
        rnn_step_kernel<<<rgrid, 512, rnn_smem>>>(
            H0h + (size_t)(p ^ 1) * BH, H0l + (size_t)(p ^ 1) * BH,
            h1h, h1l,
            Wh + (size_t)H * K2, Wl + (size_t)H * K2, b_ih + H, b_hh + H,
            Oh + (size_t)(t + 1) * BH, Ol + (size_t)(t + 1) * BH);
        p ^= 1;
    }

    dim3 fgrid(O_DIM / 256, (T_STEPS * B_SZ) / 128);  // (32, 128) = 4096 blocks
    fc_kernel<<<fgrid, 512, fc_smem>>>(Oh + BH, Ol + BH, Fh, fc_b, outp);
}

// round 11
// speedup vs baseline: 1.5250x; 1.5250x over previous
#include <cuda_runtime.h>
#include <cuda_fp16.h>
#include <stdint.h>
#include <math.h>

#define H       1024
#define O_DIM   8192
#define T_STEPS 64
#define B_SZ    256
#define BH      (B_SZ * H)
#define K2      (2 * H)

#define NSTEP_A   26     // steps handled by the persistent gated FC
#define FCA_BLOCKS 20    // 148 - 128 rnn blocks

#define PAD_R   72
#define PAD_F   40
// rnn stage (halves) [ROUND-7 VERBATIM]: Ah 0 (32x72), Al 2304, Bh 4608 (64x72), Bl 9216 ; stage=13824
#define R_AL    2304
#define R_BH    4608
#define R_BL    9216
#define R_STG   13824
// fc stage (halves): Ah 0 (128x40), Al 5120, B 10240 (256x40) ; stage=20480
#define F_AL    5120
#define F_B     10240
#define F_STG   20480

// ---- device scratch (static) ----
__device__ __half g_Wcat_hi[2 * H * K2];
__device__ __half g_Wcat_lo[2 * H * K2];
__device__ __half g_fcW_hi[O_DIM * H];
__device__ __half g_outs_hi[(T_STEPS + 1) * BH];
__device__ __half g_outs_lo[(T_STEPS + 1) * BH];
__device__ __half g_h0_hi[2 * BH];
__device__ __half g_h0_lo[2 * BH];
__device__ __half g_h1i_hi[BH];
__device__ __half g_h1i_lo[BH];
__device__ int    g_done[T_STEPS];

__device__ __forceinline__ void split2(float v, __half &hi, __half &lo) {
    hi = __float2half(v);
    lo = __float2half(v - __half2float(hi));
}

// ---- prep kernels ----
__global__ void reset_done_kernel() {
    if (threadIdx.x < T_STEPS) g_done[threadIdx.x] = 0;
}
__global__ void prep_wcat_kernel(const float* __restrict__ W_ih,
                                 const float* __restrict__ W_hh) {
    int idx = blockIdx.x * blockDim.x + threadIdx.x;
    if (idx >= 2 * H * K2) return;
    int l = idx / (H * K2);
    int rem = idx - l * (H * K2);
    int n = rem / K2, k = rem - n * K2;
    float w = (k < H) ? W_ih[(l * H + n) * H + k] : W_hh[(l * H + n) * H + (k - H)];
    split2(w, g_Wcat_hi[idx], g_Wcat_lo[idx]);
}
__global__ void prep_fcw_kernel(const float* __restrict__ fcW) {
    int idx = blockIdx.x * blockDim.x + threadIdx.x;
    if (idx >= O_DIM * H) return;
    g_fcW_hi[idx] = __float2half(fcW[idx]);
}
__global__ void prep_acts_kernel(const float* __restrict__ x,
                                 const float* __restrict__ hidden) {
    int idx = blockIdx.x * blockDim.x + threadIdx.x;
    if (idx >= 3 * BH) return;
    if (idx < BH)            split2(x[idx], g_outs_hi[idx], g_outs_lo[idx]);
    else if (idx < 2 * BH) { int j = idx - BH;     split2(hidden[j],      g_h0_hi[j],  g_h0_lo[j]); }
    else                   { int j = idx - 2 * BH; split2(hidden[BH + j], g_h1i_hi[j], g_h1i_lo[j]); }
}

// ---- helpers ----
__device__ __forceinline__ void cpasync16(void* dst, const void* src) {
    uint32_t d = (uint32_t)__cvta_generic_to_shared(dst);
    asm volatile("cp.async.cg.shared.global [%0], [%1], 16;" :: "r"(d), "l"(src));
}
__device__ __forceinline__ void cp_commit() { asm volatile("cp.async.commit_group;"); }
template <int N> __device__ __forceinline__ void cp_wait() {
    asm volatile("cp.async.wait_group %0;" :: "n"(N));
}
__device__ __forceinline__ uint32_t lds32(const __half* p) {
    return *reinterpret_cast<const uint32_t*>(p);
}
__device__ __forceinline__ void mma_f16(float* c, const uint32_t* a, const uint32_t* b) {
    asm volatile(
        "mma.sync.aligned.m16n8k16.row.col.f32.f16.f16.f32 "
        "{%0,%1,%2,%3}, {%4,%5,%6,%7}, {%8,%9}, {%0,%1,%2,%3};"
        : "+f"(c[0]), "+f"(c[1]), "+f"(c[2]), "+f"(c[3])
        : "r"(a[0]), "r"(a[1]), "r"(a[2]), "r"(a[3]), "r"(b[0]), "r"(b[1]));
}

// ---- RNN step [ROUND-7 VERBATIM + done-signal]: C = tanh([A1|A2] @ Wcat^T + b1 + b2)
// M=256,N=1024,K=2048 ; grid (16,8)=128, tile 32m x 64n, 256 thr (8 warps 2m x 4n)
__global__ __launch_bounds__(256) void rnn_step_kernel(
    const __half* __restrict__ A1h, const __half* __restrict__ A1l,
    const __half* __restrict__ A2h, const __half* __restrict__ A2l,
    const __half* __restrict__ Bh,  const __half* __restrict__ Bl,
    const float* __restrict__ bias1, const float* __restrict__ bias2,
    __half* __restrict__ Ch, __half* __restrict__ Cl, int* done_slot)
{
    extern __shared__ __align__(16) __half smem[];
    const int tid = threadIdx.x;
    const int by32 = blockIdx.y * 32, bx64 = blockIdx.x * 64;

    auto prefetch = [&](int kc, int st) {
        __half* base = smem + st * R_STG;
        const bool low = (kc < 16);
        const int k0 = (low ? kc : kc - 16) * 64;
        const __half* Ah = low ? A1h : A2h;
        const __half* Al = low ? A1l : A2l;
        {
            int r = tid >> 3, c = (tid & 7) * 8;
            cpasync16(base + r * PAD_R + c,        Ah + (by32 + r) * H + k0 + c);
            cpasync16(base + R_AL + r * PAD_R + c, Al + (by32 + r) * H + k0 + c);
        }
        const int kb = kc * 64;
        #pragma unroll
        for (int i = 0; i < 4; i++) {
            int chunk = i * 256 + tid;
            int mat = chunk >> 9, rem = chunk & 511;
            int r = rem >> 3, c = (rem & 7) * 8;
            cpasync16(base + R_BH + mat * 4608 + r * PAD_R + c,
                      (mat ? Bl : Bh) + (size_t)(bx64 + r) * K2 + kb + c);
        }
    };

    float accA[2][4], accB[2][4], accC[2][4];
    #pragma unroll
    for (int nt = 0; nt < 2; nt++)
        #pragma unroll
        for (int i = 0; i < 4; i++) { accA[nt][i] = 0.f; accB[nt][i] = 0.f; accC[nt][i] = 0.f; }

    const int lane = tid & 31, wid = tid >> 5;
    const int g = lane >> 2, tg = lane & 3;
    const int wm = wid >> 2, wn = wid & 3;

    prefetch(0, 0); cp_commit();
    prefetch(1, 1); cp_commit();
    prefetch(2, 2); cp_commit();

    for (int kc = 0; kc < 32; kc++) {
        const int st = kc & 3;
        __syncthreads();
        if (kc + 3 < 32) { prefetch(kc + 3, (kc + 3) & 3); cp_commit(); cp_wait<3>(); }
        else if (kc == 29) cp_wait<2>();
        else if (kc == 30) cp_wait<1>();
        else               cp_wait<0>();

        const __half* pAh = smem + st * R_STG;
        const __half* pAl = pAh + R_AL;
        const __half* pBh = pAh + R_BH;
        const __half* pBl = pAh + R_BL;
        #pragma unroll
        for (int kk = 0; kk < 4; kk++) {
            const int c0 = kk * 16 + tg * 2;
            const int rm = wm * 16 + g;
            uint32_t afh[4], afl[4];
            afh[0] = lds32(pAh + rm * PAD_R + c0);
            afh[1] = lds32(pAh + (rm + 8) * PAD_R + c0);
            afh[2] = lds32(pAh + rm * PAD_R + c0 + 8);
            afh[3] = lds32(pAh + (rm + 8) * PAD_R + c0 + 8);
            afl[0] = lds32(pAl + rm * PAD_R + c0);
            afl[1] = lds32(pAl + (rm + 8) * PAD_R + c0);
            afl[2] = lds32(pAl + rm * PAD_R + c0 + 8);
            afl[3] = lds32(pAl + (rm + 8) * PAD_R + c0 + 8);
            #pragma unroll
            for (int nt = 0; nt < 2; nt++) {
                int n = wn * 16 + nt * 8 + g;
                uint32_t bh[2] = { lds32(pBh + n * PAD_R + c0), lds32(pBh + n * PAD_R + c0 + 8) };
                uint32_t bl[2] = { lds32(pBl + n * PAD_R + c0), lds32(pBl + n * PAD_R + c0 + 8) };
                mma_f16(accA[nt], afh, bh);
                mma_f16(accB[nt], afl, bh);
                mma_f16(accC[nt], afh, bl);
            }
        }
    }

    #pragma unroll
    for (int nt = 0; nt < 2; nt++) {
        int r = by32 + wm * 16 + g;
        int c = bx64 + wn * 16 + nt * 8 + tg * 2;
        float bb0 = bias1[c] + bias2[c];
        float bb1 = bias1[c + 1] + bias2[c + 1];
        float v0 = tanhf(accA[nt][0] + accB[nt][0] + accC[nt][0] + bb0);
        float v1 = tanhf(accA[nt][1] + accB[nt][1] + accC[nt][1] + bb1);
        float v2 = tanhf(accA[nt][2] + accB[nt][2] + accC[nt][2] + bb0);
        float v3 = tanhf(accA[nt][3] + accB[nt][3] + accC[nt][3] + bb1);
        __half h0, l0, h1, l1; __half2 t;
        split2(v0, h0, l0); split2(v1, h1, l1);
        t.x = h0; t.y = h1; *reinterpret_cast<__half2*>(&Ch[r * H + c]) = t;
        t.x = l0; t.y = l1; *reinterpret_cast<__half2*>(&Cl[r * H + c]) = t;
        split2(v2, h0, l0); split2(v3, h1, l1);
        t.x = h0; t.y = h1; *reinterpret_cast<__half2*>(&Ch[(r + 8) * H + c]) = t;
        t.x = l0; t.y = l1; *reinterpret_cast<__half2*>(&Cl[(r + 8) * H + c]) = t;
    }

    if (done_slot) {
        __threadfence();
        __syncthreads();
        if (tid == 0) atomicAdd(done_slot, 1);
    }
}

// ---- FC tile body [ROUND-7 FC VERBATIM, parameterized by row0/col0] ----
__device__ __forceinline__ void fc_tile_compute(
    const __half* __restrict__ Ah, const __half* __restrict__ Al,
    const __half* __restrict__ Bh,
    const float* __restrict__ fcb, float* __restrict__ outp,
    __half* smem, int row0, int col0)
{
    const int tid = threadIdx.x;

    auto prefetch = [&](int kc, int st) {
        __half* base = smem + st * F_STG;
        const int k0 = kc * 32;
        #pragma unroll
        for (int i = 0; i < 2; i++) {
            int chunk = i * 512 + tid;
            int mat = chunk >> 9, rem = chunk & 511;
            int r = rem >> 2, c = (rem & 3) * 8;
            cpasync16(base + mat * F_AL + r * PAD_F + c,
                      (mat ? Al : Ah) + (size_t)(row0 + r) * H + k0 + c);
        }
        #pragma unroll
        for (int i = 0; i < 2; i++) {
            int chunk = i * 512 + tid;
            int r = chunk >> 2, c = (chunk & 3) * 8;
            cpasync16(base + F_B + r * PAD_F + c,
                      Bh + (size_t)(col0 + r) * H + k0 + c);
        }
    };

    float acc[2][8][4];
    #pragma unroll
    for (int mt = 0; mt < 2; mt++)
        #pragma unroll
        for (int nt = 0; nt < 8; nt++)
            #pragma unroll
            for (int i = 0; i < 4; i++) acc[mt][nt][i] = 0.f;

    const int lane = tid & 31, wid = tid >> 5;
    const int g = lane >> 2, tg = lane & 3;
    const int wm = wid >> 2, wn = wid & 3;

    prefetch(0, 0); cp_commit();
    for (int kc = 0; kc < 32; kc++) {
        int st = kc & 1;
        if (kc + 1 < 32) { prefetch(kc + 1, st ^ 1); cp_commit(); cp_wait<1>(); }
        else             { cp_wait<0>(); }
        __syncthreads();
        const __half* pAh = smem + st * F_STG;
        const __half* pAl = pAh + F_AL;
        const __half* pB  = pAh + F_B;
        #pragma unroll
        for (int kk = 0; kk < 2; kk++) {
            const int c0 = kk * 16 + tg * 2;
            uint32_t afh[2][4], afl[2][4];
            #pragma unroll
            for (int mt = 0; mt < 2; mt++) {
                int rm = wm * 32 + mt * 16 + g;
                afh[mt][0] = lds32(pAh + rm * PAD_F + c0);
                afh[mt][1] = lds32(pAh + (rm + 8) * PAD_F + c0);
                afh[mt][2] = lds32(pAh + rm * PAD_F + c0 + 8);
                afh[mt][3] = lds32(pAh + (rm + 8) * PAD_F + c0 + 8);
                afl[mt][0] = lds32(pAl + rm * PAD_F + c0);
                afl[mt][1] = lds32(pAl + (rm + 8) * PAD_F + c0);
                afl[mt][2] = lds32(pAl + rm * PAD_F + c0 + 8);
                afl[mt][3] = lds32(pAl + (rm + 8) * PAD_F + c0 + 8);
            }
            #pragma unroll
            for (int nt = 0; nt < 8; nt++) {
                int n = wn * 64 + nt * 8 + g;
                uint32_t bh[2] = { lds32(pB + n * PAD_F + c0), lds32(pB + n * PAD_F + c0 + 8) };
                #pragma unroll
                for (int mt = 0; mt < 2; mt++) {
                    mma_f16(acc[mt][nt], afh[mt], bh);
                    mma_f16(acc[mt][nt], afl[mt], bh);
                }
            }
        }
        __syncthreads();
    }

    #pragma unroll
    for (int mt = 0; mt < 2; mt++) {
        #pragma unroll
        for (int nt = 0; nt < 8; nt++) {
            size_t r = row0 + wm * 32 + mt * 16 + g;
            int c = col0 + wn * 64 + nt * 8 + tg * 2;
            float b0 = fcb[c], b1 = fcb[c + 1];
            float2 p0 = { acc[mt][nt][0] + b0, acc[mt][nt][1] + b1 };
            float2 p1 = { acc[mt][nt][2] + b0, acc[mt][nt][3] + b1 };
            *reinterpret_cast<float2*>(&outp[r * O_DIM + c]) = p0;
            *reinterpret_cast<float2*>(&outp[(r + 8) * O_DIM + c]) = p1;
        }
    }
}

// FC-B (post-recurrence, full chip): rows [NSTEP_A*256, 16384)
__global__ __launch_bounds__(512) void fc_kernel(
    const __half* __restrict__ Ah, const __half* __restrict__ Al,
    const __half* __restrict__ Bh,
    const float* __restrict__ fcb, float* __restrict__ outp)
{
    extern __shared__ __align__(16) __half smem[];
    fc_tile_compute(Ah, Al, Bh, fcb, outp, smem,
                    NSTEP_A * B_SZ + blockIdx.y * 128, blockIdx.x * 256);
}

// FC-A (persistent, flag-gated, FCA_BLOCKS blocks): steps [0, NSTEP_A)
__global__ __launch_bounds__(512) void fc_gated_kernel(
    const __half* __restrict__ Ah, const __half* __restrict__ Al,
    const __half* __restrict__ Bh,
    const float* __restrict__ fcb, float* __restrict__ outp)
{
    extern __shared__ __align__(16) __half smem[];
    for (int s = 0; s < NSTEP_A; s++) {
        if (threadIdx.x == 0) {
            while (atomicAdd(&g_done[s], 0) < 128) __nanosleep(128);
        }
        __syncthreads();
        __threadfence();
        // 64 tiles for this step: 2 m-tiles x 32 n-tiles
        for (int tile = blockIdx.x; tile < 64; tile += FCA_BLOCKS) {
            int row0 = s * B_SZ + (tile >> 5) * 128;
            int col0 = (tile & 31) * 256;
            __syncthreads();
            fc_tile_compute(Ah, Al, Bh, fcb, outp, smem, row0, col0);
        }
    }
}

// ---- host launcher ----
extern "C" void kernel_launch(void* const* d_in, const int* in_sizes, int n_in,
                              void* d_out, int out_size) {
    const float* x      = (const float*)d_in[0];
    const float* hidden = (const float*)d_in[1];
    const float* W_ih   = (const float*)d_in[3];
    const float* W_hh   = (const float*)d_in[4];
    const float* b_ih   = (const float*)d_in[5];
    const float* b_hh   = (const float*)d_in[6];
    const float* fc_W   = (const float*)d_in[7];
    const float* fc_b   = (const float*)d_in[8];
    float* outp = (float*)d_out;

    __half *Wh, *Wl, *Fh, *Oh, *Ol, *H0h, *H0l, *H1h, *H1l;
    int* Dn;
    cudaGetSymbolAddress((void**)&Wh,  g_Wcat_hi);
    cudaGetSymbolAddress((void**)&Wl,  g_Wcat_lo);
    cudaGetSymbolAddress((void**)&Fh,  g_fcW_hi);
    cudaGetSymbolAddress((void**)&Oh,  g_outs_hi);
    cudaGetSymbolAddress((void**)&Ol,  g_outs_lo);
    cudaGetSymbolAddress((void**)&H0h, g_h0_hi);
    cudaGetSymbolAddress((void**)&H0l, g_h0_lo);
    cudaGetSymbolAddress((void**)&H1h, g_h1i_hi);
    cudaGetSymbolAddress((void**)&H1l, g_h1i_lo);
    cudaGetSymbolAddress((void**)&Dn,  g_done);

    static cudaStream_t s1 = nullptr;
    static cudaEvent_t evFork = nullptr, evJoin = nullptr;
    if (!s1) {
        cudaStreamCreateWithFlags(&s1, cudaStreamNonBlocking);
        cudaEventCreateWithFlags(&evFork, cudaEventDisableTiming);
        cudaEventCreateWithFlags(&evJoin, cudaEventDisableTiming);
    }

    const int rnn_smem = 4 * R_STG * (int)sizeof(__half);  // 110592
    const int fc_smem  = 2 * F_STG * (int)sizeof(__half);  // 81920
    cudaFuncSetAttribute(rnn_step_kernel, cudaFuncAttributeMaxDynamicSharedMemorySize, rnn_smem);
    cudaFuncSetAttribute(fc_kernel,       cudaFuncAttributeMaxDynamicSharedMemorySize, fc_smem);
    cudaFuncSetAttribute(fc_gated_kernel, cudaFuncAttributeMaxDynamicSharedMemorySize, fc_smem);

    reset_done_kernel<<<1, 64>>>();
    prep_wcat_kernel<<<(2 * H * K2 + 255) / 256, 256>>>(W_ih, W_hh);
    prep_fcw_kernel<<<(O_DIM * H + 255) / 256, 256>>>(fc_W);
    prep_acts_kernel<<<(3 * BH + 255) / 256, 256>>>(x, hidden);

    // fork: persistent gated FC on side stream (20 blocks = spare SMs only)
    cudaEventRecord(evFork, 0);
    cudaStreamWaitEvent(s1, evFork, 0);
    fc_gated_kernel<<<FCA_BLOCKS, 512, fc_smem, s1>>>(Oh + BH, Ol + BH, Fh, fc_b, outp);
    cudaEventRecord(evJoin, s1);

    dim3 rgrid(H / 64, B_SZ / 32);   // (16, 8) = 128 blocks
    int p = 0;
    for (int t = 0; t < T_STEPS; t++) {
        rnn_step_kernel<<<rgrid, 256, rnn_smem>>>(
            Oh + (size_t)t * BH, Ol + (size_t)t * BH,
            H0h + (size_t)p * BH, H0l + (size_t)p * BH,
            Wh, Wl, b_ih, b_hh,
            H0h + (size_t)(p ^ 1) * BH, H0l + (size_t)(p ^ 1) * BH, nullptr);
        const __half* h1h = (t == 0) ? H1h : Oh + (size_t)t * BH;
        const __half* h1l = (t == 0) ? H1l : Ol + (size_t)t * BH;
        rnn_step_kernel<<<rgrid, 256, rnn_smem>>>(
            H0h + (size_t)(p ^ 1) * BH, H0l + (size_t)(p ^ 1) * BH,
            h1h, h1l,
            Wh + (size_t)H * K2, Wl + (size_t)H * K2, b_ih + H, b_hh + H,
            Oh + (size_t)(t + 1) * BH, Ol + (size_t)(t + 1) * BH, Dn + t);
        p ^= 1;
    }

    // FC-B: remaining steps on the full chip
    dim3 fgrid(O_DIM / 256, (T_STEPS - NSTEP_A) * 2);  // (32, 76)
    fc_kernel<<<fgrid, 512, fc_smem>>>(Oh + BH, Ol + BH, Fh, fc_b, outp);

    cudaStreamWaitEvent(0, evJoin, 0);
}

// round 12
// speedup vs baseline: 2.1616x; 1.4175x over previous
#include <cuda_runtime.h>
#include <cuda_fp16.h>
#include <stdint.h>
#include <math.h>

#define H       1024
#define O_DIM   8192
#define T_STEPS 64
#define B_SZ    256
#define BH      (B_SZ * H)
#define K2      (2 * H)

#define PAD_R   72
#define PAD_F   40
// rnn stage (halves) [ROUND-7 VERBATIM]: Ah 0 (32x72), Al 2304, Bh 4608 (64x72), Bl 9216 ; stage=13824
#define R_AL    2304
#define R_BH    4608
#define R_BL    9216
#define R_STG   13824
// fc stage (halves): Ah 0 (128x40), Al 5120, B 10240 (256x40) ; stage=20480
#define F_AL    5120
#define F_B     10240
#define F_STG   20480

#define RNN_BLOCKS 128

// ---- device scratch (static) ----
__device__ __half g_Wcat_hi[2 * H * K2];
__device__ __half g_Wcat_lo[2 * H * K2];
__device__ __half g_fcW_hi[O_DIM * H];
__device__ __half g_outs_hi[(T_STEPS + 1) * BH];
__device__ __half g_outs_lo[(T_STEPS + 1) * BH];
__device__ __half g_h0_hi[2 * BH];
__device__ __half g_h0_lo[2 * BH];
__device__ __half g_h1i_hi[BH];
__device__ __half g_h1i_lo[BH];
__device__ int    g_bar;

__device__ __forceinline__ void split2(float v, __half &hi, __half &lo) {
    hi = __float2half(v);
    lo = __float2half(v - __half2float(hi));
}

// ---- prep kernels ----
__global__ void reset_bar_kernel() { if (threadIdx.x == 0) g_bar = 0; }

__global__ void prep_wcat_kernel(const float* __restrict__ W_ih,
                                 const float* __restrict__ W_hh) {
    int idx = blockIdx.x * blockDim.x + threadIdx.x;
    if (idx >= 2 * H * K2) return;
    int l = idx / (H * K2);
    int rem = idx - l * (H * K2);
    int n = rem / K2, k = rem - n * K2;
    float w = (k < H) ? W_ih[(l * H + n) * H + k] : W_hh[(l * H + n) * H + (k - H)];
    split2(w, g_Wcat_hi[idx], g_Wcat_lo[idx]);
}
__global__ void prep_fcw_kernel(const float* __restrict__ fcW) {
    int idx = blockIdx.x * blockDim.x + threadIdx.x;
    if (idx >= O_DIM * H) return;
    g_fcW_hi[idx] = __float2half(fcW[idx]);
}
__global__ void prep_acts_kernel(const float* __restrict__ x,
                                 const float* __restrict__ hidden) {
    int idx = blockIdx.x * blockDim.x + threadIdx.x;
    if (idx >= 3 * BH) return;
    if (idx < BH)            split2(x[idx], g_outs_hi[idx], g_outs_lo[idx]);
    else if (idx < 2 * BH) { int j = idx - BH;     split2(hidden[j],      g_h0_hi[j],  g_h0_lo[j]); }
    else                   { int j = idx - 2 * BH; split2(hidden[BH + j], g_h1i_hi[j], g_h1i_lo[j]); }
}

// ---- helpers ----
__device__ __forceinline__ void cpasync16(void* dst, const void* src) {
    uint32_t d = (uint32_t)__cvta_generic_to_shared(dst);
    asm volatile("cp.async.cg.shared.global [%0], [%1], 16;" :: "r"(d), "l"(src));
}
__device__ __forceinline__ void cp_commit() { asm volatile("cp.async.commit_group;"); }
template <int N> __device__ __forceinline__ void cp_wait() {
    asm volatile("cp.async.wait_group %0;" :: "n"(N));
}
__device__ __forceinline__ uint32_t lds32(const __half* p) {
    return *reinterpret_cast<const uint32_t*>(p);
}
__device__ __forceinline__ void mma_f16(float* c, const uint32_t* a, const uint32_t* b) {
    asm volatile(
        "mma.sync.aligned.m16n8k16.row.col.f32.f16.f16.f32 "
        "{%0,%1,%2,%3}, {%4,%5,%6,%7}, {%8,%9}, {%0,%1,%2,%3};"
        : "+f"(c[0]), "+f"(c[1]), "+f"(c[2]), "+f"(c[3])
        : "r"(a[0]), "r"(a[1]), "r"(a[2]), "r"(a[3]), "r"(b[0]), "r"(b[1]));
}

// ---- RNN tile body [ROUND-7 VERBATIM, as device function] ----
// C = tanh([A1|A2] @ B^T + b1 + b2) for this block's 32m x 64n tile
__device__ __forceinline__ void rnn_tile(
    const __half* __restrict__ A1h, const __half* __restrict__ A1l,
    const __half* __restrict__ A2h, const __half* __restrict__ A2l,
    const __half* __restrict__ Bh,  const __half* __restrict__ Bl,
    const float* __restrict__ bias1, const float* __restrict__ bias2,
    __half* __restrict__ Ch, __half* __restrict__ Cl,
    __half* smem, int by32, int bx64)
{
    const int tid = threadIdx.x;

    auto prefetch = [&](int kc, int st) {
        __half* base = smem + st * R_STG;
        const bool low = (kc < 16);
        const int k0 = (low ? kc : kc - 16) * 64;
        const __half* Ah = low ? A1h : A2h;
        const __half* Al = low ? A1l : A2l;
        {
            int r = tid >> 3, c = (tid & 7) * 8;
            cpasync16(base + r * PAD_R + c,        Ah + (by32 + r) * H + k0 + c);
            cpasync16(base + R_AL + r * PAD_R + c, Al + (by32 + r) * H + k0 + c);
        }
        const int kb = kc * 64;
        #pragma unroll
        for (int i = 0; i < 4; i++) {
            int chunk = i * 256 + tid;
            int mat = chunk >> 9, rem = chunk & 511;
            int r = rem >> 3, c = (rem & 7) * 8;
            cpasync16(base + R_BH + mat * 4608 + r * PAD_R + c,
                      (mat ? Bl : Bh) + (size_t)(bx64 + r) * K2 + kb + c);
        }
    };

    float accA[2][4], accB[2][4], accC[2][4];
    #pragma unroll
    for (int nt = 0; nt < 2; nt++)
        #pragma unroll
        for (int i = 0; i < 4; i++) { accA[nt][i] = 0.f; accB[nt][i] = 0.f; accC[nt][i] = 0.f; }

    const int lane = tid & 31, wid = tid >> 5;
    const int g = lane >> 2, tg = lane & 3;
    const int wm = wid >> 2, wn = wid & 3;

    prefetch(0, 0); cp_commit();
    prefetch(1, 1); cp_commit();
    prefetch(2, 2); cp_commit();

    for (int kc = 0; kc < 32; kc++) {
        const int st = kc & 3;
        __syncthreads();
        if (kc + 3 < 32) { prefetch(kc + 3, (kc + 3) & 3); cp_commit(); cp_wait<3>(); }
        else if (kc == 29) cp_wait<2>();
        else if (kc == 30) cp_wait<1>();
        else               cp_wait<0>();

        const __half* pAh = smem + st * R_STG;
        const __half* pAl = pAh + R_AL;
        const __half* pBh = pAh + R_BH;
        const __half* pBl = pAh + R_BL;
        #pragma unroll
        for (int kk = 0; kk < 4; kk++) {
            const int c0 = kk * 16 + tg * 2;
            const int rm = wm * 16 + g;
            uint32_t afh[4], afl[4];
            afh[0] = lds32(pAh + rm * PAD_R + c0);
            afh[1] = lds32(pAh + (rm + 8) * PAD_R + c0);
            afh[2] = lds32(pAh + rm * PAD_R + c0 + 8);
            afh[3] = lds32(pAh + (rm + 8) * PAD_R + c0 + 8);
            afl[0] = lds32(pAl + rm * PAD_R + c0);
            afl[1] = lds32(pAl + (rm + 8) * PAD_R + c0);
            afl[2] = lds32(pAl + rm * PAD_R + c0 + 8);
            afl[3] = lds32(pAl + (rm + 8) * PAD_R + c0 + 8);
            #pragma unroll
            for (int nt = 0; nt < 2; nt++) {
                int n = wn * 16 + nt * 8 + g;
                uint32_t bh[2] = { lds32(pBh + n * PAD_R + c0), lds32(pBh + n * PAD_R + c0 + 8) };
                uint32_t bl[2] = { lds32(pBl + n * PAD_R + c0), lds32(pBl + n * PAD_R + c0 + 8) };
                mma_f16(accA[nt], afh, bh);
                mma_f16(accB[nt], afl, bh);
                mma_f16(accC[nt], afh, bl);
            }
        }
    }

    #pragma unroll
    for (int nt = 0; nt < 2; nt++) {
        int r = by32 + wm * 16 + g;
        int c = bx64 + wn * 16 + nt * 8 + tg * 2;
        float bb0 = bias1[c] + bias2[c];
        float bb1 = bias1[c + 1] + bias2[c + 1];
        float v0 = tanhf(accA[nt][0] + accB[nt][0] + accC[nt][0] + bb0);
        float v1 = tanhf(accA[nt][1] + accB[nt][1] + accC[nt][1] + bb1);
        float v2 = tanhf(accA[nt][2] + accB[nt][2] + accC[nt][2] + bb0);
        float v3 = tanhf(accA[nt][3] + accB[nt][3] + accC[nt][3] + bb1);
        __half h0, l0, h1, l1; __half2 t;
        split2(v0, h0, l0); split2(v1, h1, l1);
        t.x = h0; t.y = h1; *reinterpret_cast<__half2*>(&Ch[r * H + c]) = t;
        t.x = l0; t.y = l1; *reinterpret_cast<__half2*>(&Cl[r * H + c]) = t;
        split2(v2, h0, l0); split2(v3, h1, l1);
        t.x = h0; t.y = h1; *reinterpret_cast<__half2*>(&Ch[(r + 8) * H + c]) = t;
        t.x = l0; t.y = l1; *reinterpret_cast<__half2*>(&Cl[(r + 8) * H + c]) = t;
    }
}

// ---- persistent recurrence: 128 blocks (single wave), grid barrier between GEMMs
__global__ __launch_bounds__(256) void rnn_persistent_kernel(
    const float* __restrict__ b_ih, const float* __restrict__ b_hh)
{
    extern __shared__ __align__(16) __half smem[];
    const int by32 = blockIdx.y * 32, bx64 = blockIdx.x * 64;
    int bar_target = 0;

    auto gbar = [&]() {
        bar_target += RNN_BLOCKS;
        __syncthreads();
        if (threadIdx.x == 0) {
            __threadfence();
            atomicAdd(&g_bar, 1);
            while (atomicAdd(&g_bar, 0) < bar_target) __nanosleep(64);
        }
        __syncthreads();
    };

    int p = 0;
    for (int t = 0; t < T_STEPS; t++) {
        // layer 0: in = outs[t], h = h0[p] -> h0[p^1]
        rnn_tile(g_outs_hi + (size_t)t * BH, g_outs_lo + (size_t)t * BH,
                 g_h0_hi + (size_t)p * BH,   g_h0_lo + (size_t)p * BH,
                 g_Wcat_hi, g_Wcat_lo, b_ih, b_hh,
                 g_h0_hi + (size_t)(p ^ 1) * BH, g_h0_lo + (size_t)(p ^ 1) * BH,
                 smem, by32, bx64);
        gbar();
        // layer 1: in = h0[p^1], h = (t==0 ? h1i : outs[t]) -> outs[t+1]
        const __half* h1h = (t == 0) ? g_h1i_hi : g_outs_hi + (size_t)t * BH;
        const __half* h1l = (t == 0) ? g_h1i_lo : g_outs_lo + (size_t)t * BH;
        rnn_tile(g_h0_hi + (size_t)(p ^ 1) * BH, g_h0_lo + (size_t)(p ^ 1) * BH,
                 h1h, h1l,
                 g_Wcat_hi + (size_t)H * K2, g_Wcat_lo + (size_t)H * K2,
                 b_ih + H, b_hh + H,
                 g_outs_hi + (size_t)(t + 1) * BH, g_outs_lo + (size_t)(t + 1) * BH,
                 smem, by32, bx64);
        gbar();
        p ^= 1;
    }
}

// ---- FC (full) [ROUND-7 VERBATIM]: out = A @ fcW^T + fc_b ; M=16384,N=8192,K=1024
__global__ __launch_bounds__(512) void fc_kernel(
    const __half* __restrict__ Ah, const __half* __restrict__ Al,
    const __half* __restrict__ Bh,
    const float* __restrict__ fcb, float* __restrict__ outp)
{
    extern __shared__ __align__(16) __half smem[];
    const int tid = threadIdx.x;
    const int row0 = blockIdx.y * 128, col0 = blockIdx.x * 256;

    auto prefetch = [&](int kc, int st) {
        __half* base = smem + st * F_STG;
        const int k0 = kc * 32;
        #pragma unroll
        for (int i = 0; i < 2; i++) {
            int chunk = i * 512 + tid;
            int mat = chunk >> 9, rem = chunk & 511;
            int r = rem >> 2, c = (rem & 3) * 8;
            cpasync16(base + mat * F_AL + r * PAD_F + c,
                      (mat ? Al : Ah) + (size_t)(row0 + r) * H + k0 + c);
        }
        #pragma unroll
        for (int i = 0; i < 2; i++) {
            int chunk = i * 512 + tid;
            int r = chunk >> 2, c = (chunk & 3) * 8;
            cpasync16(base + F_B + r * PAD_F + c,
                      Bh + (size_t)(col0 + r) * H + k0 + c);
        }
    };

    float acc[2][8][4];
    #pragma unroll
    for (int mt = 0; mt < 2; mt++)
        #pragma unroll
        for (int nt = 0; nt < 8; nt++)
            #pragma unroll
            for (int i = 0; i < 4; i++) acc[mt][nt][i] = 0.f;

    const int lane = tid & 31, wid = tid >> 5;
    const int g = lane >> 2, tg = lane & 3;
    const int wm = wid >> 2, wn = wid & 3;

    prefetch(0, 0); cp_commit();
    for (int kc = 0; kc < 32; kc++) {
        int st = kc & 1;
        if (kc + 1 < 32) { prefetch(kc + 1, st ^ 1); cp_commit(); cp_wait<1>(); }
        else             { cp_wait<0>(); }
        __syncthreads();
        const __half* pAh = smem + st * F_STG;
        const __half* pAl = pAh + F_AL;
        const __half* pB  = pAh + F_B;
        #pragma unroll
        for (int kk = 0; kk < 2; kk++) {
            const int c0 = kk * 16 + tg * 2;
            uint32_t afh[2][4], afl[2][4];
            #pragma unroll
            for (int mt = 0; mt < 2; mt++) {
                int rm = wm * 32 + mt * 16 + g;
                afh[mt][0] = lds32(pAh + rm * PAD_F + c0);
                afh[mt][1] = lds32(pAh + (rm + 8) * PAD_F + c0);
                afh[mt][2] = lds32(pAh + rm * PAD_F + c0 + 8);
                afh[mt][3] = lds32(pAh + (rm + 8) * PAD_F + c0 + 8);
                afl[mt][0] = lds32(pAl + rm * PAD_F + c0);
                afl[mt][1] = lds32(pAl + (rm + 8) * PAD_F + c0);
                afl[mt][2] = lds32(pAl + rm * PAD_F + c0 + 8);
                afl[mt][3] = lds32(pAl + (rm + 8) * PAD_F + c0 + 8);
            }
            #pragma unroll
            for (int nt = 0; nt < 8; nt++) {
                int n = wn * 64 + nt * 8 + g;
                uint32_t bh[2] = { lds32(pB + n * PAD_F + c0), lds32(pB + n * PAD_F + c0 + 8) };
                #pragma unroll
                for (int mt = 0; mt < 2; mt++) {
                    mma_f16(acc[mt][nt], afh[mt], bh);
                    mma_f16(acc[mt][nt], afl[mt], bh);
                }
            }
        }
        __syncthreads();
    }

    #pragma unroll
    for (int mt = 0; mt < 2; mt++) {
        #pragma unroll
        for (int nt = 0; nt < 8; nt++) {
            size_t r = row0 + wm * 32 + mt * 16 + g;
            int c = col0 + wn * 64 + nt * 8 + tg * 2;
            float b0 = fcb[c], b1 = fcb[c + 1];
            float2 p0 = { acc[mt][nt][0] + b0, acc[mt][nt][1] + b1 };
            float2 p1 = { acc[mt][nt][2] + b0, acc[mt][nt][3] + b1 };
            *reinterpret_cast<float2*>(&outp[r * O_DIM + c]) = p0;
            *reinterpret_cast<float2*>(&outp[(r + 8) * O_DIM + c]) = p1;
        }
    }
}

// ---- host launcher ----
extern "C" void kernel_launch(void* const* d_in, const int* in_sizes, int n_in,
                              void* d_out, int out_size) {
    const float* x      = (const float*)d_in[0];
    const float* hidden = (const float*)d_in[1];
    const float* W_ih   = (const float*)d_in[3];
    const float* W_hh   = (const float*)d_in[4];
    const float* b_ih   = (const float*)d_in[5];
    const float* b_hh   = (const float*)d_in[6];
    const float* fc_W   = (const float*)d_in[7];
    const float* fc_b   = (const float*)d_in[8];
    float* outp = (float*)d_out;

    __half *Fh, *Oh, *Ol;
    cudaGetSymbolAddress((void**)&Fh, g_fcW_hi);
    cudaGetSymbolAddress((void**)&Oh, g_outs_hi);
    cudaGetSymbolAddress((void**)&Ol, g_outs_lo);

    const int rnn_smem = 4 * R_STG * (int)sizeof(__half);  // 110592
    const int fc_smem  = 2 * F_STG * (int)sizeof(__half);  // 81920
    cudaFuncSetAttribute(rnn_persistent_kernel, cudaFuncAttributeMaxDynamicSharedMemorySize, rnn_smem);
    cudaFuncSetAttribute(fc_kernel,             cudaFuncAttributeMaxDynamicSharedMemorySize, fc_smem);

    reset_bar_kernel<<<1, 32>>>();
    prep_wcat_kernel<<<(2 * H * K2 + 255) / 256, 256>>>(W_ih, W_hh);
    prep_fcw_kernel<<<(O_DIM * H + 255) / 256, 256>>>(fc_W);
    prep_acts_kernel<<<(3 * BH + 255) / 256, 256>>>(x, hidden);

    // one persistent launch for the whole recurrence (128 blocks = single wave)
    dim3 rgrid(H / 64, B_SZ / 32);   // (16, 8) = 128 blocks
    rnn_persistent_kernel<<<rgrid, 256, rnn_smem>>>(b_ih, b_hh);

    // FC strictly after
    dim3 fgrid(O_DIM / 256, (T_STEPS * B_SZ) / 128);  // (32, 128)
    fc_kernel<<<fgrid, 512, fc_smem>>>(Oh + BH, Ol + BH, Fh, fc_b, outp);
}